// round 1
// baseline (speedup 1.0000x reference)
#include <cuda_runtime.h>
#include <math.h>

#define TOK   4096          // B*N = 4*1024
#define DIM_  1024
#define HID_  4096
#define NHEAD 16
#define HDIM  64

// Scratch (allocation-free rule: __device__ globals)
__device__ float g_H  [(size_t)TOK * DIM_];        // LN output (reused for LN1 and LN2)
__device__ float g_QKV[(size_t)TOK * 3 * DIM_];    // QKV projection
__device__ float g_O  [(size_t)TOK * DIM_];        // attention output (token-major, col = h*64+d)
__device__ float g_X1 [(size_t)TOK * DIM_];        // x after attention residual
__device__ float g_G  [(size_t)TOK * HID_];        // GELU(fc1) activations

// ---------------------------------------------------------------------------
// LayerNorm: one block per row (1024 cols), 256 threads, float4 per thread
// ---------------------------------------------------------------------------
__global__ void ln_kernel(const float* __restrict__ x, const float* __restrict__ g,
                          const float* __restrict__ b, float* __restrict__ out) {
    __shared__ float red[2][8];
    int row = blockIdx.x, tid = threadIdx.x;
    const float4* xr = (const float4*)(x + (size_t)row * DIM_);
    float4 v = xr[tid];
    float s  = v.x + v.y + v.z + v.w;
    float sq = v.x*v.x + v.y*v.y + v.z*v.z + v.w*v.w;
    #pragma unroll
    for (int o = 16; o > 0; o >>= 1) {
        s  += __shfl_xor_sync(0xffffffffu, s,  o);
        sq += __shfl_xor_sync(0xffffffffu, sq, o);
    }
    int wid = tid >> 5, lid = tid & 31;
    if (lid == 0) { red[0][wid] = s; red[1][wid] = sq; }
    __syncthreads();
    s = 0.f; sq = 0.f;
    #pragma unroll
    for (int i = 0; i < 8; i++) { s += red[0][i]; sq += red[1][i]; }
    float mean = s * (1.0f / DIM_);
    float var  = sq * (1.0f / DIM_) - mean * mean;
    float rstd = rsqrtf(var + 1e-5f);
    float4 gg = ((const float4*)g)[tid];
    float4 bb = ((const float4*)b)[tid];
    float4 o4;
    o4.x = (v.x - mean) * rstd * gg.x + bb.x;
    o4.y = (v.y - mean) * rstd * gg.y + bb.y;
    o4.z = (v.z - mean) * rstd * gg.z + bb.z;
    o4.w = (v.w - mean) * rstd * gg.w + bb.w;
    ((float4*)(out + (size_t)row * DIM_))[tid] = o4;
}

// ---------------------------------------------------------------------------
// GEMM: C[M,N] = A[M,K] * B[N,K]^T + bias[N]  (+ epilogue)
//   EPI 0: bias only
//   EPI 1: bias + exact GELU
//   EPI 2: bias + residual add (res[M,N])
// 128x128 tile, BK=16, 256 threads, 8x8 microtile.
// ---------------------------------------------------------------------------
template <int EPI>
__global__ void __launch_bounds__(256, 2)
gemm_tn(const float* __restrict__ A, const float* __restrict__ B,
        const float* __restrict__ bias, const float* __restrict__ res,
        float* __restrict__ C, int M, int N, int K) {
    __shared__ float As[16][128];
    __shared__ float Bs[16][128];
    const int tid = threadIdx.x;
    const int tx = tid & 15, ty = tid >> 4;
    const float* Ab = A + (size_t)blockIdx.y * 128 * K;
    const float* Bb = B + (size_t)blockIdx.x * 128 * K;

    float acc[8][8];
    #pragma unroll
    for (int i = 0; i < 8; i++)
        #pragma unroll
        for (int j = 0; j < 8; j++) acc[i][j] = 0.f;

    for (int k0 = 0; k0 < K; k0 += 16) {
        #pragma unroll
        for (int l = 0; l < 2; l++) {
            int idx = tid + l * 256;          // 0..511
            int row = idx >> 2;               // 0..127
            int kc  = (idx & 3) << 2;         // 0,4,8,12
            float4 va = *(const float4*)(Ab + (size_t)row * K + k0 + kc);
            As[kc+0][row] = va.x; As[kc+1][row] = va.y;
            As[kc+2][row] = va.z; As[kc+3][row] = va.w;
            float4 vb = *(const float4*)(Bb + (size_t)row * K + k0 + kc);
            Bs[kc+0][row] = vb.x; Bs[kc+1][row] = vb.y;
            Bs[kc+2][row] = vb.z; Bs[kc+3][row] = vb.w;
        }
        __syncthreads();
        #pragma unroll
        for (int kk = 0; kk < 16; kk++) {
            float4 a0 = *(float4*)&As[kk][ty * 8];
            float4 a1 = *(float4*)&As[kk][ty * 8 + 4];
            float4 b0 = *(float4*)&Bs[kk][tx * 8];
            float4 b1 = *(float4*)&Bs[kk][tx * 8 + 4];
            float a[8] = {a0.x,a0.y,a0.z,a0.w,a1.x,a1.y,a1.z,a1.w};
            float b[8] = {b0.x,b0.y,b0.z,b0.w,b1.x,b1.y,b1.z,b1.w};
            #pragma unroll
            for (int i = 0; i < 8; i++)
                #pragma unroll
                for (int j = 0; j < 8; j++)
                    acc[i][j] += a[i] * b[j];
        }
        __syncthreads();
    }

    int crow0 = blockIdx.y * 128 + ty * 8;
    int ccol0 = blockIdx.x * 128 + tx * 8;
    float bv[8];
    #pragma unroll
    for (int j = 0; j < 8; j++) bv[j] = bias[ccol0 + j];
    #pragma unroll
    for (int i = 0; i < 8; i++) {
        size_t roff = (size_t)(crow0 + i) * N + ccol0;
        #pragma unroll
        for (int j = 0; j < 8; j++) {
            float v = acc[i][j] + bv[j];
            if (EPI == 1) v = 0.5f * v * (1.0f + erff(v * 0.70710678118654752f));
            if (EPI == 2) v += res[roff + j];
            C[roff + j] = v;
        }
    }
}

// ---------------------------------------------------------------------------
// Flash attention, fp32. Grid: (64 batch-heads, 8 query tiles of 128).
// Smem: Qs[128][64] row-major, Kt[64][128] k-major, Vs[128][64] row-major,
//       Ps[128][128]. Online softmax, 8 rows x (8 score / 4 out) per thread.
// ---------------------------------------------------------------------------
__global__ void __launch_bounds__(256, 1)
attn_kernel(const float* __restrict__ QKV, float* __restrict__ O) {
    extern __shared__ float sm[];
    float* Qs = sm;                // 8192
    float* Kt = sm + 8192;         // 8192
    float* Vs = sm + 16384;        // 8192
    float* Ps = sm + 24576;        // 16384
    const int bb = blockIdx.x >> 4, h = blockIdx.x & 15;
    const int q0 = blockIdx.y * 128;
    const int tid = threadIdx.x;
    const int tx = tid & 15, ty = tid >> 4;
    const size_t base = (size_t)bb * 1024 * 3072 + (size_t)h * 64;
    const float scale = 0.125f;    // 64^-0.5

    // Load Q tile (pre-scaled)
    for (int i = tid; i < 2048; i += 256) {
        int r = i >> 4, c4 = (i & 15) << 2;
        float4 v = *(const float4*)(QKV + base + (size_t)(q0 + r) * 3072 + c4);
        v.x *= scale; v.y *= scale; v.z *= scale; v.w *= scale;
        *(float4*)&Qs[r * 64 + c4] = v;
    }

    float m_i[8], l_i[8], o[8][4];
    #pragma unroll
    for (int i = 0; i < 8; i++) {
        m_i[i] = -1e30f; l_i[i] = 0.f;
        #pragma unroll
        for (int j = 0; j < 4; j++) o[i][j] = 0.f;
    }

    for (int kt = 0; kt < 8; kt++) {
        __syncthreads();   // covers Q load on first iter, previous tile readers after
        for (int i = tid; i < 2048; i += 256) {
            int r = i >> 4, c4 = (i & 15) << 2;
            const float* src = QKV + base + (size_t)(kt * 128 + r) * 3072;
            float4 kv = *(const float4*)(src + 1024 + c4);
            Kt[(c4 + 0) * 128 + r] = kv.x;
            Kt[(c4 + 1) * 128 + r] = kv.y;
            Kt[(c4 + 2) * 128 + r] = kv.z;
            Kt[(c4 + 3) * 128 + r] = kv.w;
            *(float4*)&Vs[r * 64 + c4] = *(const float4*)(src + 2048 + c4);
        }
        __syncthreads();

        // S = Qs * K^T
        float s[8][8];
        #pragma unroll
        for (int i = 0; i < 8; i++)
            #pragma unroll
            for (int j = 0; j < 8; j++) s[i][j] = 0.f;
        for (int kk = 0; kk < 64; kk++) {
            float a[8];
            #pragma unroll
            for (int i = 0; i < 8; i++) a[i] = Qs[(ty * 8 + i) * 64 + kk];
            float4 b0 = *(float4*)&Kt[kk * 128 + tx * 8];
            float4 b1 = *(float4*)&Kt[kk * 128 + tx * 8 + 4];
            float b[8] = {b0.x,b0.y,b0.z,b0.w,b1.x,b1.y,b1.z,b1.w};
            #pragma unroll
            for (int i = 0; i < 8; i++)
                #pragma unroll
                for (int j = 0; j < 8; j++)
                    s[i][j] += a[i] * b[j];
        }

        // Online softmax (row groups = 16 contiguous lanes in one warp half)
        #pragma unroll
        for (int i = 0; i < 8; i++) {
            float mx = s[i][0];
            #pragma unroll
            for (int j = 1; j < 8; j++) mx = fmaxf(mx, s[i][j]);
            #pragma unroll
            for (int off = 8; off > 0; off >>= 1)
                mx = fmaxf(mx, __shfl_xor_sync(0xffffffffu, mx, off));
            float m_new = fmaxf(m_i[i], mx);
            float corr = __expf(m_i[i] - m_new);
            float p[8], rs = 0.f;
            #pragma unroll
            for (int j = 0; j < 8; j++) { p[j] = __expf(s[i][j] - m_new); rs += p[j]; }
            #pragma unroll
            for (int off = 8; off > 0; off >>= 1)
                rs += __shfl_xor_sync(0xffffffffu, rs, off);
            l_i[i] = l_i[i] * corr + rs;
            m_i[i] = m_new;
            #pragma unroll
            for (int j = 0; j < 4; j++) o[i][j] *= corr;
            *(float4*)&Ps[(ty * 8 + i) * 128 + tx * 8]     = make_float4(p[0],p[1],p[2],p[3]);
            *(float4*)&Ps[(ty * 8 + i) * 128 + tx * 8 + 4] = make_float4(p[4],p[5],p[6],p[7]);
        }
        __syncwarp();   // Ps rows are produced & consumed within the same 16-lane group

        // O += P * V
        for (int kk = 0; kk < 128; kk++) {
            float4 vv = *(float4*)&Vs[kk * 64 + tx * 4];
            #pragma unroll
            for (int i = 0; i < 8; i++) {
                float pp = Ps[(ty * 8 + i) * 128 + kk];
                o[i][0] += pp * vv.x; o[i][1] += pp * vv.y;
                o[i][2] += pp * vv.z; o[i][3] += pp * vv.w;
            }
        }
    }

    #pragma unroll
    for (int i = 0; i < 8; i++) {
        float inv = 1.0f / l_i[i];
        int tok = bb * 1024 + q0 + ty * 8 + i;
        float4 r = make_float4(o[i][0]*inv, o[i][1]*inv, o[i][2]*inv, o[i][3]*inv);
        *(float4*)&O[(size_t)tok * 1024 + h * 64 + tx * 4] = r;
    }
}

// ---------------------------------------------------------------------------
extern "C" void kernel_launch(void* const* d_in, const int* in_sizes, int n_in,
                              void* d_out, int out_size) {
    const float* x      = (const float*)d_in[0];
    const float* ln1_g  = (const float*)d_in[1];
    const float* ln1_b  = (const float*)d_in[2];
    const float* qkv_w  = (const float*)d_in[3];
    const float* qkv_b  = (const float*)d_in[4];
    const float* proj_w = (const float*)d_in[5];
    const float* proj_b = (const float*)d_in[6];
    const float* ln2_g  = (const float*)d_in[7];
    const float* ln2_b  = (const float*)d_in[8];
    const float* fc1_w  = (const float*)d_in[9];
    const float* fc1_b  = (const float*)d_in[10];
    const float* fc2_w  = (const float*)d_in[11];
    const float* fc2_b  = (const float*)d_in[12];
    float* out = (float*)d_out;

    float *H, *QKV, *O, *X1, *G;
    cudaGetSymbolAddress((void**)&H,   g_H);
    cudaGetSymbolAddress((void**)&QKV, g_QKV);
    cudaGetSymbolAddress((void**)&O,   g_O);
    cudaGetSymbolAddress((void**)&X1,  g_X1);
    cudaGetSymbolAddress((void**)&G,   g_G);

    cudaFuncSetAttribute(attn_kernel,
                         cudaFuncAttributeMaxDynamicSharedMemorySize, 163840);

    // 1) LN1
    ln_kernel<<<TOK, 256>>>(x, ln1_g, ln1_b, H);
    // 2) QKV = H @ qkv_w^T + b              [4096, 3072]
    gemm_tn<0><<<dim3(3072/128, TOK/128), 256>>>(H, qkv_w, qkv_b, nullptr, QKV,
                                                 TOK, 3072, DIM_);
    // 3) attention -> O                      [4096, 1024]
    attn_kernel<<<dim3(64, 8), 256, 163840>>>(QKV, O);
    // 4) X1 = x + O @ proj_w^T + b
    gemm_tn<2><<<dim3(DIM_/128, TOK/128), 256>>>(O, proj_w, proj_b, x, X1,
                                                 TOK, DIM_, DIM_);
    // 5) LN2
    ln_kernel<<<TOK, 256>>>(X1, ln2_g, ln2_b, H);
    // 6) G = gelu(H @ fc1_w^T + b)           [4096, 4096]
    gemm_tn<1><<<dim3(HID_/128, TOK/128), 256>>>(H, fc1_w, fc1_b, nullptr, G,
                                                 TOK, HID_, DIM_);
    // 7) out = X1 + G @ fc2_w^T + b
    gemm_tn<2><<<dim3(DIM_/128, TOK/128), 256>>>(G, fc2_w, fc2_b, X1, out,
                                                 TOK, DIM_, HID_);
}